// round 4
// baseline (speedup 1.0000x reference)
#include <cuda_runtime.h>
#include <cstdint>

// CostBuilder: stereo cost-volume construction.
// left, right: (B=4, C=32, H=64, W=128) fp32
// out:         (B, 2C=64, D=48, H, W) fp32
//   out[b, c,   d, h, w] = (w>=d) ? left [b,c,h,w]   : 0
//   out[b, C+c, d, h, w] = (w>=d) ? right[b,c,h,w-d] : 0
//
// R4: bypass the per-thread L1 store pipeline. Compute each 32KB output
// d-plane into SMEM staging, then write it with cp.async.bulk (TMA bulk
// store, shared->global). Double-buffered so compute overlaps TMA reads.

namespace {
constexpr int B   = 4;
constexpr int C   = 32;
constexpr int H   = 64;
constexpr int W   = 128;
constexpr int D   = 48;               // MAX_DISP / 4
constexpr int HW  = H * W;            // 8192 floats = 32KB
constexpr int TPB = 256;
constexpr int DPB = 6;                // d values per block
constexpr int NDG = D / DPB;          // 8 d-groups
constexpr int PASSES = HW / 4 / TPB;  // 8 float4 passes per plane
constexpr int SMEM_BYTES = 3 * HW * 4;  // input plane + 2 staging buffers

// Per-row bank swizzle for the input plane: pos(w) = (w%4)*32 + w/4.
// Lane-parallel access at w = 4*lane + e gives consecutive banks.
__device__ __forceinline__ int swz(int w) { return ((w & 3) << 5) | (w >> 2); }

__device__ __forceinline__ uint32_t smem_u32(const void* p) {
    return (uint32_t)__cvta_generic_to_shared(p);
}
__device__ __forceinline__ void bulk_store_s2g(void* gptr, uint32_t saddr, uint32_t bytes) {
    asm volatile("cp.async.bulk.global.shared::cta.bulk_group [%0], [%1], %2;"
                 :: "l"(gptr), "r"(saddr), "r"(bytes) : "memory");
}
__device__ __forceinline__ void bulk_commit() {
    asm volatile("cp.async.bulk.commit_group;" ::: "memory");
}
template <int N> __device__ __forceinline__ void bulk_wait_read() {
    asm volatile("cp.async.bulk.wait_group.read %0;" :: "n"(N) : "memory");
}
template <int N> __device__ __forceinline__ void bulk_wait() {
    asm volatile("cp.async.bulk.wait_group %0;" :: "n"(N) : "memory");
}
__device__ __forceinline__ void fence_async_shared() {
    asm volatile("fence.proxy.async.shared::cta;" ::: "memory");
}
}

__global__ __launch_bounds__(TPB) void cost_builder_kernel(
    const float* __restrict__ left,
    const float* __restrict__ right,
    float* __restrict__ out)
{
    extern __shared__ float smem[];
    float* s_in  = smem;                 // swizzled input plane (32KB)
    float* s_out[2] = { smem + HW, smem + 2 * HW };  // staging (2x32KB)

    const int g   = blockIdx.x;
    const int dg  = g & (NDG - 1);       // d-group 0..7
    const int bc2 = g >> 3;              // output channel-plane 0..255
    const int b   = bc2 >> 6;
    const int ch  = bc2 & 63;
    const bool is_right = ch >= C;
    const int c   = ch & (C - 1);

    const float* src = (is_right ? right : left) + (size_t)(b * C + c) * HW;

    const int tid  = threadIdx.x;
    const int lane = tid & 31;

    // Stage input plane into swizzled shared (conflict-free STS).
    #pragma unroll
    for (int p = 0; p < PASSES; ++p) {
        const int i = p * TPB + tid;
        const float4 v = reinterpret_cast<const float4*>(src)[i];
        const int rowbase = (i >> 5) * W;
        s_in[rowbase +  0 + lane] = v.x;
        s_in[rowbase + 32 + lane] = v.y;
        s_in[rowbase + 64 + lane] = v.z;
        s_in[rowbase + 96 + lane] = v.w;
    }
    __syncthreads();

    float* outplane0 = out + (size_t)bc2 * D * HW + (size_t)(dg * DPB) * HW;

    #pragma unroll
    for (int dd = 0; dd < DPB; ++dd) {
        const int d     = dg * DPB + dd;
        const int shift = is_right ? d : 0;
        float* sbuf = s_out[dd & 1];

        // Ensure the TMA issued 2 iterations ago has finished READING sbuf.
        if (dd >= 2) {
            if (tid == 0) bulk_wait_read<1>();
            __syncthreads();
        }

        // Compute masked/shifted plane into staging (conflict-free STS.128).
        #pragma unroll
        for (int p = 0; p < PASSES; ++p) {
            const int i = p * TPB + tid;
            const int rowbase = (i >> 5) * W;
            const int w  = lane << 2;
            const int q0 = w - shift;

            float4 v;
            v.x = (w     >= d) ? s_in[rowbase + swz(q0     < 0 ? 0 : q0    )] : 0.0f;
            v.y = (w + 1 >= d) ? s_in[rowbase + swz(q0 + 1 < 0 ? 0 : q0 + 1)] : 0.0f;
            v.z = (w + 2 >= d) ? s_in[rowbase + swz(q0 + 2 < 0 ? 0 : q0 + 2)] : 0.0f;
            v.w = (w + 3 >= d) ? s_in[rowbase + swz(q0 + 3 < 0 ? 0 : q0 + 3)] : 0.0f;
            reinterpret_cast<float4*>(sbuf)[i] = v;
        }

        // Order generic STS before async-proxy read, then launch bulk store.
        fence_async_shared();
        __syncthreads();
        if (tid == 0) {
            bulk_store_s2g(outplane0 + (size_t)dd * HW, smem_u32(sbuf), HW * 4);
            bulk_commit();
        }
    }

    // Drain all bulk stores before exit.
    if (tid == 0) bulk_wait<0>();
}

extern "C" void kernel_launch(void* const* d_in, const int* in_sizes, int n_in,
                              void* d_out, int out_size)
{
    const float* left  = (const float*)d_in[0];
    const float* right = (const float*)d_in[1];
    float* out = (float*)d_out;

    static bool attr_done = false;
    if (!attr_done) {
        cudaFuncSetAttribute(cost_builder_kernel,
                             cudaFuncAttributeMaxDynamicSharedMemorySize, SMEM_BYTES);
        attr_done = true;
    }

    const int grid = (2 * B * C) * NDG;   // 256 planes * 8 d-groups = 2048
    cost_builder_kernel<<<grid, TPB, SMEM_BYTES>>>(left, right, out);
}

// round 5
// speedup vs baseline: 1.0668x; 1.0668x over previous
#include <cuda_runtime.h>
#include <cstdint>

// CostBuilder: stereo cost-volume construction.
// left, right: (B=4, C=32, H=64, W=128) fp32
// out:         (B, 2C=64, D=48, H, W) fp32
//   out[b, c,   d, h, w] = (w>=d) ? left [b,c,h,w]   : 0
//   out[b, C+c, d, h, w] = (w>=d) ? right[b,c,h,w-d] : 0
//
// R5: R3 layout (one block = plane x 3 consecutive d = 96KB contiguous
// output), single controlled change: __stcs -> __stwt (write-through).
// Hypothesis: steady write-through pacing beats bursty L2 dirty writeback.

namespace {
constexpr int B   = 4;
constexpr int C   = 32;
constexpr int H   = 64;
constexpr int W   = 128;
constexpr int D   = 48;              // MAX_DISP / 4
constexpr int HW  = H * W;           // 8192
constexpr int TPB = 256;
constexpr int DPB = 3;               // d values per block
constexpr int NDG = D / DPB;         // 16 d-groups
constexpr int PASSES = HW / 4 / TPB; // 8 float4 passes per plane

// Per-row bank swizzle: pos(w) = (w%4)*32 + w/4. For lane-parallel access at
// w = 4*lane + e, idx>>2 = lane + const -> consecutive banks, conflict-free.
__device__ __forceinline__ int swz(int w) { return ((w & 3) << 5) | (w >> 2); }
}

__global__ __launch_bounds__(TPB) void cost_builder_kernel(
    const float* __restrict__ left,
    const float* __restrict__ right,
    float* __restrict__ out)
{
    const int g    = blockIdx.x;
    const int dg   = g & (NDG - 1);      // d-group 0..15
    const int bc2  = g >> 4;             // output channel-plane 0..255
    const int b    = bc2 >> 6;
    const int ch   = bc2 & 63;
    const bool is_right = ch >= C;
    const int c    = ch & (C - 1);

    const float* src = (is_right ? right : left) + (size_t)(b * C + c) * HW;

    __shared__ float s[HW];              // 32KB plane, per-row swizzled

    const int tid  = threadIdx.x;
    const int lane = tid & 31;

    // Stage input plane into swizzled shared (conflict-free STS per element).
    #pragma unroll
    for (int p = 0; p < PASSES; ++p) {
        const int i = p * TPB + tid;
        const float4 v = reinterpret_cast<const float4*>(src)[i];
        const int rowbase = (i >> 5) * W;
        s[rowbase +  0 + lane] = v.x;
        s[rowbase + 32 + lane] = v.y;
        s[rowbase + 64 + lane] = v.z;
        s[rowbase + 96 + lane] = v.w;
    }
    __syncthreads();

    // This block's contiguous output region: plane bc2, d in [d0, d0+DPB).
    const unsigned outbase0 = (unsigned)bc2 * D * HW;
    const int d0 = dg * DPB;

    #pragma unroll
    for (int dd = 0; dd < DPB; ++dd) {
        const int d     = d0 + dd;
        const int shift = is_right ? d : 0;
        float4* outp = reinterpret_cast<float4*>(out + outbase0 + (unsigned)d * HW);

        #pragma unroll
        for (int p = 0; p < PASSES; ++p) {
            const int i = p * TPB + tid;
            const int rowbase = (i >> 5) * W;
            const int w  = lane << 2;            // warp spans one full row
            const int q0 = w - shift;

            float4 v;
            // Clamp keeps speculative LDS in-bounds; mask selects 0 for w<d.
            v.x = (w     >= d) ? s[rowbase + swz(q0     < 0 ? 0 : q0    )] : 0.0f;
            v.y = (w + 1 >= d) ? s[rowbase + swz(q0 + 1 < 0 ? 0 : q0 + 1)] : 0.0f;
            v.z = (w + 2 >= d) ? s[rowbase + swz(q0 + 2 < 0 ? 0 : q0 + 2)] : 0.0f;
            v.w = (w + 3 >= d) ? s[rowbase + swz(q0 + 3 < 0 ? 0 : q0 + 3)] : 0.0f;

            __stwt(outp + i, v);                 // write-through streaming store
        }
    }
}

extern "C" void kernel_launch(void* const* d_in, const int* in_sizes, int n_in,
                              void* d_out, int out_size)
{
    const float* left  = (const float*)d_in[0];
    const float* right = (const float*)d_in[1];
    float* out = (float*)d_out;

    const int grid = (2 * B * C) * NDG;   // 256 planes * 16 d-groups = 4096
    cost_builder_kernel<<<grid, TPB>>>(left, right, out);
}